// round 8
// baseline (speedup 1.0000x reference)
#include <cuda_runtime.h>
#include <cstdint>
#include <math.h>

#define BATCH   4
#define SEQ     2048
#define DMODEL  1024
#define DINNER  2048
#define DSTATE  64
#define MROWS   (BATCH*SEQ)      /* 8192 */
#define NPROJ   (2*DSTATE+1)     /* 129  */
#define NCH     16               /* scan chunks */
#define CHLEN   (SEQ/NCH)        /* 128 */

// ---------------- scratch (device globals; no allocations allowed) ----------
__device__ float g_xi  [MROWS*DINNER];
__device__ float g_sz  [MROWS*DINNER];
__device__ float g_bx  [MROWS*DINNER];
__device__ float g_Cm  [MROWS*DINNER];
__device__ float g_y   [MROWS*DINNER];        // sigma-permuted k layout
__device__ float g_pBC [MROWS*128];
__device__ float g_dsum[MROWS];
__device__ float g_a   [MROWS];
__device__ float g_hend [BATCH*NCH*DINNER];
__device__ float g_carry[BATCH*NCH*DINNER];
__device__ float g_prodA[BATCH*NCH];
__device__ float g_xr  [MROWS*DMODEL];        // rounded x, sigma k layout
__device__ float g_WrT [2*DINNER*DMODEL];     // W_in  -> [4096][1024] sigma, tf32
__device__ float g_WorT[DMODEL*DINNER];       // W_out -> [1024][2048] sigma, tf32
__device__ float g_WxhT[128*DINNER];          // W_xp[:,1:] -> [128][2048] sigma hi
__device__ float g_WxlT[128*DINNER];          //                               lo
__device__ float g_WBhT[DINNER*DSTATE];       // W_B -> [2048][64] sigma, tf32
__device__ float g_WChT[DINNER*DSTATE];       // W_C -> [2048][64] sigma, tf32

// ---------------- helpers ---------------------------------------------------
__device__ __forceinline__ uint32_t smem_u32(const void* p) {
    uint32_t a;
    asm("{ .reg .u64 t; cvta.to.shared.u64 t, %1; cvt.u32.u64 %0, t; }" : "=r"(a) : "l"(p));
    return a;
}
__device__ __forceinline__ float tf32r(float x) {
    float y; asm("cvt.rna.tf32.f32 %0, %1;" : "=f"(y) : "f"(x)); return y;
}
__device__ __forceinline__ void cp16(uint32_t s, const void* g) {
    asm volatile("cp.async.cg.shared.global [%0], [%1], 16;" :: "r"(s), "l"(g));
}
#define CP_COMMIT asm volatile("cp.async.commit_group;" ::: "memory")
#define CP_WAIT1  asm volatile("cp.async.wait_group 1;" ::: "memory")
#define CP_WAIT0  asm volatile("cp.async.wait_group 0;" ::: "memory")

__device__ __forceinline__ void mma8(float* c, const uint32_t* a, const uint32_t* b) {
    asm volatile(
        "mma.sync.aligned.m16n8k8.row.col.f32.tf32.tf32.f32 "
        "{%0,%1,%2,%3}, {%4,%5,%6,%7}, {%8,%9}, {%0,%1,%2,%3};"
        : "+f"(c[0]), "+f"(c[1]), "+f"(c[2]), "+f"(c[3])
        : "r"(a[0]), "r"(a[1]), "r"(a[2]), "r"(a[3]), "r"(b[0]), "r"(b[1]));
}

// ---------------- fused prep kernel -----------------------------------------
// sigma within each k 8-group: logical q stored at pos (q<4 ? 2q : 2(q-4)+1)
__device__ __forceinline__ void do_transpose(
    const float* __restrict__ src, int sstride, int scol0,
    float* __restrict__ dh, float* __restrict__ dl, int K,
    int kt, int nt, int t, float (*sm)[33])
{
    int tx = t & 31, ty = t >> 5;          // ty 0..7
    int k0 = kt * 32, n0 = nt * 32;
#pragma unroll
    for (int r = 0; r < 4; r++)
        sm[ty + 8 * r][tx] = src[(size_t)(k0 + ty + 8 * r) * sstride + scol0 + n0 + tx];
    __syncthreads();
    int kl = (tx & ~7) + ((tx & 1) * 4 + ((tx >> 1) & 3));   // inverse sigma
#pragma unroll
    for (int r = 0; r < 4; r++) {
        int nn = ty + 8 * r;
        float v = sm[kl][nn];
        float h = tf32r(v);
        dh[(size_t)(n0 + nn) * K + k0 + tx] = h;
        if (dl) dl[(size_t)(n0 + nn) * K + k0 + tx] = tf32r(v - h);
    }
}

__global__ __launch_bounds__(256)
void prep_kernel(const float* __restrict__ x, const float* __restrict__ W_in,
                 const float* __restrict__ W_out, const float* __restrict__ W_xp,
                 const float* __restrict__ W_B, const float* __restrict__ W_C)
{
    __shared__ float sm[32][33];
    int s = blockIdx.x, t = threadIdx.x;

    if (s < 4096) {   // x -> g_xr: round + sigma-permute k (8 el/thread)
        size_t base = (size_t)s * 2048 + t * 8;
        float4 a = *(const float4*)(x + base);
        float4 b = *(const float4*)(x + base + 4);
        float4 o1, o2;
        o1.x = tf32r(a.x); o1.y = tf32r(b.x); o1.z = tf32r(a.y); o1.w = tf32r(b.y);
        o2.x = tf32r(a.z); o2.y = tf32r(b.z); o2.z = tf32r(a.w); o2.w = tf32r(b.w);
        *(float4*)(g_xr + base) = o1;
        *(float4*)(g_xr + base + 4) = o2;
        return;
    }
    s -= 4096;
    if (s < 4096) { do_transpose(W_in, 4096, 0, g_WrT, nullptr, 1024, s & 31, s >> 5, t, sm); return; }
    s -= 4096;
    if (s < 2048) { do_transpose(W_out, 1024, 0, g_WorT, nullptr, 2048, s & 63, s >> 6, t, sm); return; }
    s -= 2048;
    if (s < 256)  { do_transpose(W_xp, NPROJ, 1, g_WxhT, g_WxlT, 2048, s & 63, s >> 6, t, sm); return; }
    s -= 256;
    if (s < 128)  { do_transpose(W_B, 2048, 0, g_WBhT, nullptr, 64, s & 1, s >> 1, t, sm); return; }
    s -= 128;
    if (s < 128)  { do_transpose(W_C, 2048, 0, g_WChT, nullptr, 64, s & 1, s >> 1, t, sm); return; }
    s -= 128;
    float4 z4 = make_float4(0.f, 0.f, 0.f, 0.f);
    if (s < 1024) { *(float4*)(g_pBC + (size_t)s * 1024 + t * 4) = z4; return; }
    s -= 1024;
    *(float4*)(g_dsum + (size_t)s * 1024 + t * 4) = z4;   // 8 blocks
}

// ======================= tf32 mma.sync GEMM (B transposed sigma) ============
// C[M,N] = A[M,K] @ W[N,K]^T.  Block tile 128x128, BK=32, 256 thr.
// APAIR: A pre-rounded + sigma layout -> paired LDS.64 frag loads.
// PRECISE: 3xtf32 (A split in-loop, B hi/lo prebuilt). 2 stages, else 3.
// MODE 0: C0=v  MODE 1: xi/silu split + delta dot  MODE 2: C0=v*aux
// MODE 3: atomicAdd (split-K)
#define TN_SMEM 110592

template <int MODE, bool PRECISE, bool APAIR>
__global__ void __launch_bounds__(256, 2)
gemm_tn(const float* __restrict__ A, int lda,
        const float* __restrict__ B, const float* __restrict__ Bl, int ldb,
        float* __restrict__ C0, float* __restrict__ C1,
        const float* __restrict__ auxw,
        int N, int K)
{
    constexpr int NSTG = PRECISE ? 2 : 3;
    constexpr uint32_t STG = PRECISE ? 55296u : 36864u;

    extern __shared__ char smem[];
    const uint32_t sbase = smem_u32(smem);
    float* fs = (float*)smem;

    const int t    = threadIdx.x;
    const int lane = t & 31;
    const int wid  = t >> 5;
    const int warpM = wid & 3;
    const int warpN = wid >> 2;

    int bx = blockIdx.x, by = blockIdx.y;
    {
        int lin = by * gridDim.x + bx;
        int per = gridDim.x * 8;
        int p = lin / per, rem = lin % per;
        by = p * 8 + (rem & 7);
        bx = rem >> 3;
    }
    const int rowBase = by * 128;
    const int colBase = bx * 128;
    const int kBase   = blockIdx.z * K;

    float acc[2][8][4];
#pragma unroll
    for (int i = 0; i < 2; i++)
#pragma unroll
        for (int j = 0; j < 8; j++)
#pragma unroll
            for (int q = 0; q < 4; q++) acc[i][j][q] = 0.0f;

    const int nkt = K / 32;

    auto issue = [&](int st, int kt) {
        const int k0 = kBase + kt * 32;
        const uint32_t sA  = sbase + (uint32_t)st * STG;
        const uint32_t sB  = sA + 18432u;
#pragma unroll
        for (int e = 0; e < 4; e++) {
            int id = t + 256 * e;
            int r = id >> 3, q = id & 7;
            cp16(sA + (uint32_t)(r * 36 + q * 4) * 4,
                 A + (size_t)(rowBase + r) * lda + k0 + q * 4);
        }
#pragma unroll
        for (int e = 0; e < 4; e++) {
            int id = t + 256 * e;
            int r = id >> 3, q = id & 7;
            cp16(sB + (uint32_t)(r * 36 + q * 4) * 4,
                 B + (size_t)(colBase + r) * ldb + k0 + q * 4);
        }
        if (PRECISE) {
            const uint32_t sBl = sB + 18432u;
#pragma unroll
            for (int e = 0; e < 4; e++) {
                int id = t + 256 * e;
                int r = id >> 3, q = id & 7;
                cp16(sBl + (uint32_t)(r * 36 + q * 4) * 4,
                     Bl + (size_t)(colBase + r) * ldb + k0 + q * 4);
            }
        }
    };

    issue(0, 0);
    CP_COMMIT;
    if (NSTG == 3 && nkt > 1) { issue(1, 1); CP_COMMIT; }

    const int r0 = warpM * 32 + (lane >> 2);
    const int kq = lane & 3;
    const int cl = warpN * 64 + (lane >> 2);

    for (int kt = 0; kt < nkt; kt++) {
        if (NSTG == 3) {
            if (kt + 1 < nkt) CP_WAIT1; else CP_WAIT0;
            __syncthreads();
            if (kt + 2 < nkt) { issue((kt + 2) % 3, kt + 2); CP_COMMIT; }
        } else {
            if (kt + 1 < nkt) { issue((kt + 1) & 1, kt + 1); CP_COMMIT; CP_WAIT1; }
            else              { CP_WAIT0; }
            __syncthreads();
        }

        const uint32_t aS = (uint32_t)(kt % NSTG) * (STG / 4);
        const uint32_t bS = aS + 4608;
        const uint32_t blS = bS + 4608;
#pragma unroll
        for (int ks = 0; ks < 4; ks++) {
            const int kb = ks * 8;
            uint32_t af[2][4], afl[2][4];
            if (APAIR) {
#pragma unroll
                for (int mt = 0; mt < 2; mt++) {
                    int rr = r0 + mt * 16;
                    float2 p0 = *(const float2*)&fs[aS + rr * 36 + kb + 2 * kq];
                    float2 p1 = *(const float2*)&fs[aS + (rr + 8) * 36 + kb + 2 * kq];
                    af[mt][0] = __float_as_uint(p0.x);
                    af[mt][1] = __float_as_uint(p1.x);
                    af[mt][2] = __float_as_uint(p0.y);
                    af[mt][3] = __float_as_uint(p1.y);
                }
            } else {
#pragma unroll
                for (int mt = 0; mt < 2; mt++) {
                    int rr = r0 + mt * 16;
                    float a0 = fs[aS + (rr    ) * 36 + kb + kq];
                    float a1 = fs[aS + (rr + 8) * 36 + kb + kq];
                    float a2 = fs[aS + (rr    ) * 36 + kb + kq + 4];
                    float a3 = fs[aS + (rr + 8) * 36 + kb + kq + 4];
                    float h0 = tf32r(a0), h1 = tf32r(a1), h2 = tf32r(a2), h3 = tf32r(a3);
                    af[mt][0] = __float_as_uint(h0); af[mt][1] = __float_as_uint(h1);
                    af[mt][2] = __float_as_uint(h2); af[mt][3] = __float_as_uint(h3);
                    if (PRECISE) {
                        afl[mt][0] = __float_as_uint(tf32r(a0 - h0));
                        afl[mt][1] = __float_as_uint(tf32r(a1 - h1));
                        afl[mt][2] = __float_as_uint(tf32r(a2 - h2));
                        afl[mt][3] = __float_as_uint(tf32r(a3 - h3));
                    }
                }
            }
#pragma unroll
            for (int nt = 0; nt < 8; nt++) {
                int cc = cl + nt * 8;
                float2 pb = *(const float2*)&fs[bS + cc * 36 + kb + 2 * kq];
                uint32_t bf[2] = { __float_as_uint(pb.x), __float_as_uint(pb.y) };
                if (PRECISE) {
                    float2 pl = *(const float2*)&fs[blS + cc * 36 + kb + 2 * kq];
                    uint32_t bfl[2] = { __float_as_uint(pl.x), __float_as_uint(pl.y) };
#pragma unroll
                    for (int mt = 0; mt < 2; mt++) {
                        mma8(acc[mt][nt], af[mt],  bfl);
                        mma8(acc[mt][nt], afl[mt], bf);
                        mma8(acc[mt][nt], af[mt],  bf);
                    }
                } else {
#pragma unroll
                    for (int mt = 0; mt < 2; mt++)
                        mma8(acc[mt][nt], af[mt], bf);
                }
            }
        }
        if (NSTG == 2) __syncthreads();
    }

    // ---- epilogue
    float* C = C0;
    int cbase = colBase;
    bool do_silu = false;
    int cstride = N;
    if (MODE == 1) {
        cstride = DINNER;
        if (colBase >= DINNER) { C = C1; cbase = colBase - DINNER; do_silu = true; }
    }

    float ds[4] = {0.0f, 0.0f, 0.0f, 0.0f};

#pragma unroll
    for (int mt = 0; mt < 2; mt++) {
#pragma unroll
        for (int nt = 0; nt < 8; nt++) {
            int gr = rowBase + warpM * 32 + mt * 16 + (lane >> 2);
            int gc = cbase + warpN * 64 + nt * 8 + 2 * (lane & 3);
            float w0a = 0.0f, w0b = 0.0f;
            if (MODE == 1 && !do_silu) {
                w0a = __ldg(&auxw[(size_t)gc * NPROJ]);
                w0b = __ldg(&auxw[(size_t)(gc + 1) * NPROJ]);
            }
#pragma unroll
            for (int h = 0; h < 2; h++) {
                float v0 = acc[mt][nt][2 * h];
                float v1 = acc[mt][nt][2 * h + 1];
                int r = gr + h * 8;
                if (MODE == 1) {
                    if (do_silu) {
                        v0 = v0 / (1.0f + expf(-v0));
                        v1 = v1 / (1.0f + expf(-v1));
                    } else {
                        ds[mt * 2 + h] += v0 * w0a + v1 * w0b;
                    }
                }
                if (MODE == 2) {
                    float2 a2 = *reinterpret_cast<const float2*>(auxw + (size_t)r * N + gc);
                    v0 *= a2.x; v1 *= a2.y;
                }
                if (MODE == 3) {
                    atomicAdd(C + (size_t)r * cstride + gc,     v0);
                    atomicAdd(C + (size_t)r * cstride + gc + 1, v1);
                } else {
                    float2 o; o.x = v0; o.y = v1;
                    *reinterpret_cast<float2*>(C + (size_t)r * cstride + gc) = o;
                }
            }
        }
    }

    if (MODE == 1 && !do_silu) {
#pragma unroll
        for (int i = 0; i < 4; i++) {
            float v = ds[i];
            v += __shfl_xor_sync(0xFFFFFFFFu, v, 1);
            v += __shfl_xor_sync(0xFFFFFFFFu, v, 2);
            if ((lane & 3) == 0) {
                int r = rowBase + warpM * 32 + (i >> 1) * 16 + (i & 1) * 8 + (lane >> 2);
                atomicAdd(&g_dsum[r], v);
            }
        }
    }
}

// ---------------- softplus -> A_bar + chunk products ------------------------
__global__ __launch_bounds__(128)
void softprod_kernel(const float* __restrict__ A_log)
{
    int m = blockIdx.x * 128 + threadIdx.x;
    float v = g_dsum[m];
    float sp = (v > 20.0f) ? v : log1pf(expf(v));
    float a = expf(-expf(A_log[0]) * sp);
    g_a[m] = a;
    float p = a;
#pragma unroll
    for (int o = 16; o; o >>= 1) p *= __shfl_xor_sync(0xFFFFFFFFu, p, o);
    __shared__ float red[4];
    if ((threadIdx.x & 31) == 0) red[threadIdx.x >> 5] = p;
    __syncthreads();
    if (threadIdx.x == 0)
        g_prodA[blockIdx.x] = red[0] * red[1] * red[2] * red[3];
}

// ---------------- parallel scan ---------------------------------------------
__global__ __launch_bounds__(256)
void scanA_kernel()
{
    int b = blockIdx.x >> 4, c = blockIdx.x & 15;
    int d = blockIdx.y * 256 + threadIdx.x;
    int s0 = c * CHLEN;
    float h = 0.0f;
    size_t base = ((size_t)b * SEQ + s0) * DINNER + d;
    int arow = b * SEQ + s0;
#pragma unroll 4
    for (int i = 0; i < CHLEN; i++)
        h = fmaf(g_a[arow + i], h, g_bx[base + (size_t)i * DINNER]);
    g_hend[(size_t)(b * NCH + c) * DINNER + d] = h;
}

__global__ __launch_bounds__(256)
void scanB_kernel()
{
    int b = blockIdx.x >> 3;
    int d = (blockIdx.x & 7) * 256 + threadIdx.x;
    float carry = 0.0f;
#pragma unroll
    for (int c = 0; c < NCH; c++) {
        size_t idx = (size_t)(b * NCH + c) * DINNER + d;
        g_carry[idx] = carry;
        carry = g_hend[idx] + g_prodA[b * NCH + c] * carry;
    }
}

// re-scan + y = tf32((C*h + D*xi)*silu(z)), written at sigma-permuted column
__global__ __launch_bounds__(256)
void scanC_kernel(const float* __restrict__ D)
{
    int b = blockIdx.x >> 4, c = blockIdx.x & 15;
    int d = blockIdx.y * 256 + threadIdx.x;
    int s0 = c * CHLEN;
    int q = d & 7;
    int sd = (d & ~7) + (q < 4 ? 2 * q : 2 * (q - 4) + 1);
    float Dd = D[d];
    float h = g_carry[(size_t)(b * NCH + c) * DINNER + d];
    size_t base  = ((size_t)b * SEQ + s0) * DINNER + d;
    size_t ybase = ((size_t)b * SEQ + s0) * DINNER + sd;
    int arow = b * SEQ + s0;
#pragma unroll 4
    for (int i = 0; i < CHLEN; i++) {
        size_t idx = base + (size_t)i * DINNER;
        float xi = g_xi[idx];
        h = fmaf(g_a[arow + i], h, g_bx[idx]);
        float y = fmaf(g_Cm[idx], h, Dd * xi);
        g_y[ybase + (size_t)i * DINNER] = tf32r(y * g_sz[idx]);
    }
}

// ---------------- launch ----------------------------------------------------
extern "C" void kernel_launch(void* const* d_in, const int* in_sizes, int n_in,
                              void* d_out, int out_size)
{
    const float* x     = (const float*)d_in[0];
    const float* W_in  = (const float*)d_in[1];
    const float* W_xp  = (const float*)d_in[2];
    const float* W_B   = (const float*)d_in[3];
    const float* W_C   = (const float*)d_in[4];
    const float* W_out = (const float*)d_in[5];
    const float* Dvec  = (const float*)d_in[6];
    const float* A_log = (const float*)d_in[7];
    float* out = (float*)d_out;

    float *p_xi, *p_sz, *p_bx, *p_Cm, *p_y, *p_pBC, *p_xr;
    float *p_WrT, *p_WorT, *p_WxhT, *p_WxlT, *p_WBhT, *p_WChT;
    cudaGetSymbolAddress((void**)&p_xi,   g_xi);
    cudaGetSymbolAddress((void**)&p_sz,   g_sz);
    cudaGetSymbolAddress((void**)&p_bx,   g_bx);
    cudaGetSymbolAddress((void**)&p_Cm,   g_Cm);
    cudaGetSymbolAddress((void**)&p_y,    g_y);
    cudaGetSymbolAddress((void**)&p_pBC,  g_pBC);
    cudaGetSymbolAddress((void**)&p_xr,   g_xr);
    cudaGetSymbolAddress((void**)&p_WrT,  g_WrT);
    cudaGetSymbolAddress((void**)&p_WorT, g_WorT);
    cudaGetSymbolAddress((void**)&p_WxhT, g_WxhT);
    cudaGetSymbolAddress((void**)&p_WxlT, g_WxlT);
    cudaGetSymbolAddress((void**)&p_WBhT, g_WBhT);
    cudaGetSymbolAddress((void**)&p_WChT, g_WChT);

    cudaFuncSetAttribute(gemm_tn<1,false,true>,  cudaFuncAttributeMaxDynamicSharedMemorySize, TN_SMEM);
    cudaFuncSetAttribute(gemm_tn<0,false,true>,  cudaFuncAttributeMaxDynamicSharedMemorySize, TN_SMEM);
    cudaFuncSetAttribute(gemm_tn<3,true,false>,  cudaFuncAttributeMaxDynamicSharedMemorySize, TN_SMEM);
    cudaFuncSetAttribute(gemm_tn<2,false,false>, cudaFuncAttributeMaxDynamicSharedMemorySize, TN_SMEM);
    cudaFuncSetAttribute(gemm_tn<0,false,false>, cudaFuncAttributeMaxDynamicSharedMemorySize, TN_SMEM);

    // 0) fused prep: xr, all weight reshapes, zero pBC/dsum
    prep_kernel<<<11784, 256>>>(x, W_in, W_out, W_xp, W_B, W_C);

    // 1) xz = x @ W_in -> xi, silu(z); fused delta dot -> g_dsum
    gemm_tn<1,false,true><<<dim3(32, 64), 256, TN_SMEM>>>(
        p_xr, DMODEL, p_WrT, nullptr, DMODEL, p_xi, p_sz, W_xp, 2 * DINNER, DMODEL);

    // 2) softplus -> A_bar + chunk products
    softprod_kernel<<<BATCH * NCH, 128>>>(A_log);

    // 3) [B_raw|C_raw] = xi @ W_xp[:,1:129]  (split-K x8, 3xtf32)
    gemm_tn<3,true,false><<<dim3(1, 64, 8), 256, TN_SMEM>>>(
        p_xi, DINNER, p_WxhT, p_WxlT, DINNER, p_pBC, nullptr, nullptr, 128, DINNER / 8);

    // 4) bx = (B_raw @ W_B) * xi   (single tf32)
    gemm_tn<2,false,false><<<dim3(16, 64), 256, TN_SMEM>>>(
        p_pBC, 128, p_WBhT, nullptr, DSTATE, p_bx, nullptr, p_xi, DINNER, DSTATE);

    // 5) Cm = C_raw @ W_C          (single tf32)
    gemm_tn<0,false,false><<<dim3(16, 64), 256, TN_SMEM>>>(
        p_pBC + 64, 128, p_WChT, nullptr, DSTATE, p_Cm, nullptr, nullptr, DINNER, DSTATE);

    // 6) parallel scan
    scanA_kernel<<<dim3(BATCH * NCH, DINNER / 256), 256>>>();
    scanB_kernel<<<BATCH * (DINNER / 256), 256>>>();
    scanC_kernel<<<dim3(BATCH * NCH, DINNER / 256), 256>>>(Dvec);

    // 7) out = y @ W_out
    gemm_tn<0,false,true><<<dim3(8, 64), 256, TN_SMEM>>>(
        p_y, DINNER, p_WorT, nullptr, DINNER, out, nullptr, nullptr, DMODEL, DINNER);
}